// round 13
// baseline (speedup 1.0000x reference)
#include <cuda_runtime.h>
#include <cuda_bf16.h>
#include <stdint.h>
#include <math.h>

// ---------------------------------------------------------------------------
// Problem constants
// ---------------------------------------------------------------------------
#define RR 128
#define CC 256
#define EE 768
#define HH 12
#define DD 64
#define MTOK (RR * CC)            // 32768 tokens
#define QSCALE (0.0110485434560398f)   // (1/8) / sqrt(128)
#define RSPLIT 16
#define RCHUNK (RR / RSPLIT)      // 8

// ---------------------------------------------------------------------------
// Dense tiling: CTA 128x256, BK=32, 8 warps (4M x 2N), 3-stage cp.async
// ---------------------------------------------------------------------------
#define BM 128
#define BN 256
#define BK 32
#define NKB (EE / BK)             // 24
#define SROW 64                   // bytes per smem row (32 bf16), swizzled
#define A_PL (BM * SROW)          // 8192
#define B_PL (BN * SROW)          // 16384
#define ST_AHI 0
#define ST_ALO A_PL
#define ST_BHI (2 * A_PL)
#define ST_BLO (2 * A_PL + B_PL)
#define STAGE_B (2 * A_PL + 2 * B_PL)   // 49152
#define NSTAGE 3
#define GSMEM (NSTAGE * STAGE_B)        // 147456

// context tiling: CTA 128(i) x [4r x 64d], K=j 32/blk
#define CT_AHI 0                         // P hi: 128 x 64B = 8192
#define CT_ALO 8192                      // P lo
#define CT_B   16384                     // 4 r regions x (hi 4096 + lo 4096)
#define CSTAGE_B (16384 + 4 * 8192)      // 49152
#define CGSMEM (NSTAGE * CSTAGE_B)       // 147456

// ---------------------------------------------------------------------------
// Device global scratch: separate hi / lo bf16 planes
// ---------------------------------------------------------------------------
__device__ __nv_bfloat16 g_xh[(size_t)MTOK * EE], g_xl[(size_t)MTOK * EE];
__device__ __nv_bfloat16 g_wth[4 * (size_t)EE * EE], g_wtl[4 * (size_t)EE * EE];
__device__ __nv_bfloat16 g_qh[(size_t)MTOK * EE],  g_ql[(size_t)MTOK * EE];
__device__ __nv_bfloat16 g_kh[(size_t)MTOK * EE],  g_kl[(size_t)MTOK * EE];
__device__ __nv_bfloat16 g_vh[(size_t)MTOK * EE],  g_vl[(size_t)MTOK * EE];
__device__ __nv_bfloat16 g_ch[(size_t)MTOK * EE],  g_cl[(size_t)MTOK * EE];
__device__ __nv_bfloat16 g_ph[(size_t)HH * CC * CC], g_pl[(size_t)HH * CC * CC];
__device__ float         g_lpart[(size_t)RSPLIT * HH * CC * CC];

// ---------------------------------------------------------------------------
// Helpers
// ---------------------------------------------------------------------------
__device__ __forceinline__ uint32_t smem_to_u32(const void* p) {
    uint32_t a;
    asm("{ .reg .u64 t; cvta.to.shared.u64 t, %1; cvt.u32.u64 %0, t; }"
        : "=r"(a) : "l"(p));
    return a;
}

#define CP16(saddr, gptr) \
    asm volatile("cp.async.cg.shared.global [%0], [%1], 16;" \
        :: "r"(saddr), "l"(gptr) : "memory")
#define CPCOMMIT() asm volatile("cp.async.commit_group;" ::: "memory")
#define CPWAIT0()  asm volatile("cp.async.wait_group 0;" ::: "memory")
#define CPWAIT1()  asm volatile("cp.async.wait_group 1;" ::: "memory")

#define LDSM4(r, addr) \
    asm volatile("ldmatrix.sync.aligned.m8n8.x4.shared.b16 {%0,%1,%2,%3}, [%4];" \
        : "=r"((r)[0]), "=r"((r)[1]), "=r"((r)[2]), "=r"((r)[3]) : "r"(addr))

#define LDSM4T(r, addr) \
    asm volatile("ldmatrix.sync.aligned.m8n8.x4.trans.shared.b16 {%0,%1,%2,%3}, [%4];" \
        : "=r"((r)[0]), "=r"((r)[1]), "=r"((r)[2]), "=r"((r)[3]) : "r"(addr))

__device__ __forceinline__ void mma_bf16(float* c, const uint32_t* a,
                                         uint32_t b0, uint32_t b1) {
    asm volatile(
        "mma.sync.aligned.m16n8k16.row.col.f32.bf16.bf16.f32 "
        "{%0,%1,%2,%3}, {%4,%5,%6,%7}, {%8,%9}, {%0,%1,%2,%3};"
        : "+f"(c[0]), "+f"(c[1]), "+f"(c[2]), "+f"(c[3])
        : "r"(a[0]), "r"(a[1]), "r"(a[2]), "r"(a[3]), "r"(b0), "r"(b1));
}

// 3-term split MMA group: ah*bh + ah*bl + al*bh into two 16x8 accs
__device__ __forceinline__ void mma3x2(
    float* c0, float* c1, const uint32_t* ah, const uint32_t* al,
    const uint32_t* bh, const uint32_t* bl)
{
    mma_bf16(c0, ah, bh[0], bh[1]);
    mma_bf16(c0, ah, bl[0], bl[1]);
    mma_bf16(c0, al, bh[0], bh[1]);
    mma_bf16(c1, ah, bh[2], bh[3]);
    mma_bf16(c1, ah, bl[2], bl[3]);
    mma_bf16(c1, al, bh[2], bh[3]);
}

__device__ __forceinline__ void split_bf16(float f, __nv_bfloat16& h, __nv_bfloat16& l) {
    h = __float2bfloat16(f);
    l = __float2bfloat16(f - __bfloat162float(h));
}

__device__ __forceinline__ void store_split2(
    __nv_bfloat16* Ph, __nv_bfloat16* Pl, size_t idx, float v0, float v1)
{
    __nv_bfloat16 h0, l0, h1, l1;
    split_bf16(v0, h0, l0);
    split_bf16(v1, h1, l1);
    uint32_t uh = (uint32_t)__bfloat16_as_ushort(h0) | ((uint32_t)__bfloat16_as_ushort(h1) << 16);
    uint32_t ul = (uint32_t)__bfloat16_as_ushort(l0) | ((uint32_t)__bfloat16_as_ushort(l1) << 16);
    *(uint32_t*)(Ph + idx) = uh;
    *(uint32_t*)(Pl + idx) = ul;
}

// swizzled smem address: 64B rows, 4 chunks of 16B, chunk ^= (row>>1)&3
__device__ __forceinline__ uint32_t swz(int row, int chunk) {
    return (uint32_t)(row * SROW) + (uint32_t)(((chunk ^ ((row >> 1) & 3)) << 4));
}

// ---------------------------------------------------------------------------
// Pack kernels
// ---------------------------------------------------------------------------
__global__ __launch_bounds__(256) void pack_x_kernel(const float* __restrict__ x)
{
    size_t idx = (size_t)blockIdx.x * 256 + threadIdx.x;
    float4 v = ((const float4*)x)[idx];
    store_split2(g_xh, g_xl, idx * 4,     v.x, v.y);
    store_split2(g_xh, g_xl, idx * 4 + 2, v.z, v.w);
}

__global__ __launch_bounds__(256) void pack_wt_kernel(
    const float* __restrict__ wq, const float* __restrict__ wk,
    const float* __restrict__ wv, const float* __restrict__ wo)
{
    const int mat = blockIdx.z;
    const float* W = (mat == 0) ? wq : (mat == 1) ? wk : (mat == 2) ? wv : wo;
    __shared__ float s[32][33];
    const int k0 = blockIdx.y * 32, n0 = blockIdx.x * 32;
    const int tx = threadIdx.x & 31, ty = threadIdx.x >> 5;
#pragma unroll
    for (int i = 0; i < 32; i += 8)
        s[ty + i][tx] = W[(size_t)(k0 + ty + i) * EE + n0 + tx];
    __syncthreads();
    __nv_bfloat16* dh = g_wth + (size_t)mat * EE * EE;
    __nv_bfloat16* dl = g_wtl + (size_t)mat * EE * EE;
#pragma unroll
    for (int i = 0; i < 32; i += 8) {
        __nv_bfloat16 h, l;
        split_bf16(s[tx][ty + i], h, l);
        size_t di = (size_t)(n0 + ty + i) * EE + k0 + tx;
        dh[di] = h;
        dl[di] = l;
    }
}

// ---------------------------------------------------------------------------
// Dense fragment addressing
// ---------------------------------------------------------------------------
struct Frag {
    uint32_t arb0, arb1, axr0, axr1;
    uint32_t brb[8], bxr[8];
    uint32_t acs, bcs;
};

__device__ __forceinline__ Frag make_frag(int lane, int wy, int wx) {
    Frag f;
    const int ar0 = wy * 32 + (lane & 15);
    const int ar1 = ar0 + 16;
    f.arb0 = (uint32_t)(ar0 * SROW); f.axr0 = (uint32_t)((ar0 >> 1) & 3);
    f.arb1 = (uint32_t)(ar1 * SROW); f.axr1 = (uint32_t)((ar1 >> 1) & 3);
    const int br = wx * 128 + ((lane >> 4) & 1) * 8 + (lane & 7);
#pragma unroll
    for (int np = 0; np < 8; np++) {
        const int r = br + np * 16;
        f.brb[np] = (uint32_t)(r * SROW);
        f.bxr[np] = (uint32_t)((r >> 1) & 3);
    }
    f.acs = (uint32_t)(lane >> 4);
    f.bcs = (uint32_t)((lane >> 3) & 1);
    return f;
}

__device__ __forceinline__ void compute_block(
    uint32_t base, const Frag& f, float acc[2][16][4])
{
#pragma unroll
    for (int ks = 0; ks < 2; ks++) {
        const uint32_t ca = f.acs + (uint32_t)(ks * 2);
        uint32_t ah0[4], ah1[4], al0[4], al1[4];
        LDSM4(ah0, base + ST_AHI + f.arb0 + ((ca ^ f.axr0) << 4));
        LDSM4(ah1, base + ST_AHI + f.arb1 + ((ca ^ f.axr1) << 4));
        LDSM4(al0, base + ST_ALO + f.arb0 + ((ca ^ f.axr0) << 4));
        LDSM4(al1, base + ST_ALO + f.arb1 + ((ca ^ f.axr1) << 4));
        const uint32_t cb = f.bcs + (uint32_t)(ks * 2);
#pragma unroll
        for (int np = 0; np < 8; np++) {
            uint32_t bh[4], bl[4];
            const uint32_t bo = ((cb ^ f.bxr[np]) << 4);
            LDSM4(bh, base + ST_BHI + f.brb[np] + bo);
            LDSM4(bl, base + ST_BLO + f.brb[np] + bo);
            mma3x2(acc[0][np * 2], acc[0][np * 2 + 1], ah0, al0, bh, bl);
            mma3x2(acc[1][np * 2], acc[1][np * 2 + 1], ah1, al1, bh, bl);
        }
    }
}

// loader: A 128 rows at arow0.., B 256 rows at brow0.., k offset kelem
__device__ __forceinline__ void cpload_ab(
    uint32_t base, const __nv_bfloat16* Ah, const __nv_bfloat16* Al,
    const __nv_bfloat16* Bh, const __nv_bfloat16* Bl,
    int arow0, int brow0, int kelem, int tid)
{
    const int r = tid >> 2;              // 0..63
    const int kc = tid & 3;
    const size_t go = (size_t)kelem + kc * 8;
#pragma unroll
    for (int half = 0; half < 2; half++) {
        const int row = r + half * 64;
        const uint32_t so = swz(row, kc);
        CP16(base + ST_AHI + so, Ah + (size_t)(arow0 + row) * EE + go);
        CP16(base + ST_ALO + so, Al + (size_t)(arow0 + row) * EE + go);
    }
#pragma unroll
    for (int q = 0; q < 4; q++) {
        const int row = r + q * 64;
        const uint32_t so = swz(row, kc);
        CP16(base + ST_BHI + so, Bh + (size_t)(brow0 + row) * EE + go);
        CP16(base + ST_BLO + so, Bl + (size_t)(brow0 + row) * EE + go);
    }
}

// ---------------------------------------------------------------------------
// Stages 1 & 5: dense GEMM. out = (A @ Bt^T + bias) * scale
// ---------------------------------------------------------------------------
template<bool PACK>
__device__ void gemm_mma_body(
    const __nv_bfloat16* __restrict__ Ah, const __nv_bfloat16* __restrict__ Al,
    const __nv_bfloat16* __restrict__ Bh, const __nv_bfloat16* __restrict__ Bl,
    const float* __restrict__ bias, void* __restrict__ Cout0, void* __restrict__ Cout1,
    float scale, int m0, int n0)
{
    extern __shared__ char smem[];
    const uint32_t sb = smem_to_u32(smem);
    const int tid  = threadIdx.x;
    const int lane = tid & 31;
    const int w    = tid >> 5;
    const int wy   = w & 3;
    const int wx   = w >> 2;
    const Frag f = make_frag(lane, wy, wx);

    float acc[2][16][4];
#pragma unroll
    for (int mi = 0; mi < 2; mi++)
#pragma unroll
        for (int nf = 0; nf < 16; nf++)
#pragma unroll
            for (int r = 0; r < 4; r++) acc[mi][nf][r] = 0.0f;

    cpload_ab(sb, Ah, Al, Bh, Bl, m0, n0, 0, tid);
    CPCOMMIT();
    cpload_ab(sb + STAGE_B, Ah, Al, Bh, Bl, m0, n0, BK, tid);
    CPCOMMIT();

    uint32_t bufo[3] = {sb, sb + STAGE_B, sb + 2 * STAGE_B};
#pragma unroll 1
    for (int kb = 0; kb < NKB; kb++) {
        if (kb == NKB - 1) { CPWAIT0(); } else { CPWAIT1(); }
        __syncthreads();
        compute_block(bufo[kb % 3], f, acc);
        if (kb + 2 < NKB) {
            cpload_ab(bufo[(kb + 2) % 3], Ah, Al, Bh, Bl, m0, n0, (kb + 2) * BK, tid);
            CPCOMMIT();
        }
    }

    const int mbase = m0 + wy * 32 + (lane >> 2);
    const int nbase = n0 + wx * 128 + (lane & 3) * 2;
    float2 bb[16];
#pragma unroll
    for (int nf = 0; nf < 16; nf++)
        bb[nf] = *(const float2*)(bias + nbase + nf * 8);

#pragma unroll
    for (int mi = 0; mi < 2; mi++) {
#pragma unroll
        for (int rr = 0; rr < 2; rr++) {
            const int m = mbase + mi * 16 + rr * 8;
#pragma unroll
            for (int nf = 0; nf < 16; nf++) {
                float v0 = (acc[mi][nf][rr * 2]     + bb[nf].x) * scale;
                float v1 = (acc[mi][nf][rr * 2 + 1] + bb[nf].y) * scale;
                size_t idx = (size_t)m * EE + nbase + nf * 8;
                if (PACK) {
                    store_split2((__nv_bfloat16*)Cout0, (__nv_bfloat16*)Cout1, idx, v0, v1);
                } else {
                    float2 v; v.x = v0; v.y = v1;
                    *(float2*)((float*)Cout0 + idx) = v;
                }
            }
        }
    }
}

__global__ __launch_bounds__(256, 1) void qkv_mma_kernel(
    const float* __restrict__ bq, const float* __restrict__ bk,
    const float* __restrict__ bv)
{
    const int which = blockIdx.z;
    const __nv_bfloat16* Bh = g_wth + (size_t)which * EE * EE;
    const __nv_bfloat16* Bl = g_wtl + (size_t)which * EE * EE;
    const float* bias = (which == 0) ? bq : (which == 1) ? bk : bv;
    __nv_bfloat16* oh = (which == 0) ? g_qh : (which == 1) ? g_kh : g_vh;
    __nv_bfloat16* ol = (which == 0) ? g_ql : (which == 1) ? g_kl : g_vl;
    const float scale = (which == 0) ? QSCALE : 1.0f;
    gemm_mma_body<true>(g_xh, g_xl, Bh, Bl, bias, oh, ol, scale,
                        blockIdx.y * BM, blockIdx.x * BN);
}

__global__ __launch_bounds__(256, 1) void out_mma_kernel(
    const float* __restrict__ bo, float* __restrict__ out)
{
    gemm_mma_body<false>(g_ch, g_cl, g_wth + (size_t)3 * EE * EE,
                         g_wtl + (size_t)3 * EE * EE, bo, out, nullptr, 1.0f,
                         blockIdx.y * BM, blockIdx.x * BN);
}

// ---------------------------------------------------------------------------
// Stage 2: tied-row logits, split-K over r. grid = (2 m-tiles, HH, RSPLIT)
// N = 256 (all j). k-block kk: rows (r0+kk/2)*CC, k elems h*64 + (kk&1)*32
// ---------------------------------------------------------------------------
__global__ __launch_bounds__(256, 1) void logits_mma_kernel()
{
    const int h  = blockIdx.y;
    const int r0 = blockIdx.z * RCHUNK;
    const int m0 = blockIdx.x * 128;
    const int NKK = RCHUNK * 2;               // 16

    extern __shared__ char smem[];
    const uint32_t sb = smem_to_u32(smem);
    const int tid  = threadIdx.x;
    const int lane = tid & 31;
    const int w    = tid >> 5;
    const int wy   = w & 3;
    const int wx   = w >> 2;
    const Frag f = make_frag(lane, wy, wx);

    float acc[2][16][4];
#pragma unroll
    for (int mi = 0; mi < 2; mi++)
#pragma unroll
        for (int nf = 0; nf < 16; nf++)
#pragma unroll
            for (int r = 0; r < 4; r++) acc[mi][nf][r] = 0.0f;

    auto arow = [&](int kk) { return (r0 + (kk >> 1)) * CC + m0; };
    auto brow = [&](int kk) { return (r0 + (kk >> 1)) * CC; };
    auto kel  = [&](int kk) { return h * DD + (kk & 1) * 32; };

    cpload_ab(sb, g_qh, g_ql, g_kh, g_kl, arow(0), brow(0), kel(0), tid);
    CPCOMMIT();
    cpload_ab(sb + STAGE_B, g_qh, g_ql, g_kh, g_kl, arow(1), brow(1), kel(1), tid);
    CPCOMMIT();

    uint32_t bufo[3] = {sb, sb + STAGE_B, sb + 2 * STAGE_B};
#pragma unroll 1
    for (int kk = 0; kk < NKK; kk++) {
        if (kk == NKK - 1) { CPWAIT0(); } else { CPWAIT1(); }
        __syncthreads();
        compute_block(bufo[kk % 3], f, acc);
        if (kk + 2 < NKK) {
            cpload_ab(bufo[(kk + 2) % 3], g_qh, g_ql, g_kh, g_kl,
                      arow(kk + 2), brow(kk + 2), kel(kk + 2), tid);
            CPCOMMIT();
        }
    }

    float* P = g_lpart + ((size_t)blockIdx.z * HH + h) * CC * CC;
    const int mbase = m0 + wy * 32 + (lane >> 2);
    const int nbase = wx * 128 + (lane & 3) * 2;
#pragma unroll
    for (int mi = 0; mi < 2; mi++) {
#pragma unroll
        for (int rr = 0; rr < 2; rr++) {
            const int m = mbase + mi * 16 + rr * 8;
#pragma unroll
            for (int nf = 0; nf < 16; nf++) {
                float2 v;
                v.x = acc[mi][nf][rr * 2];
                v.y = acc[mi][nf][rr * 2 + 1];
                *(float2*)(P + (size_t)m * CC + nbase + nf * 8) = v;
            }
        }
    }
}

// ---------------------------------------------------------------------------
// Stage 3: split-K reduce + softmax + split-pack. grid = HH*CC
// ---------------------------------------------------------------------------
__global__ __launch_bounds__(256) void softmax_kernel()
{
    const size_t row = blockIdx.x;
    const int t = threadIdx.x;
    __shared__ float red[256];

    float v = 0.0f;
#pragma unroll
    for (int rs = 0; rs < RSPLIT; rs++)
        v += g_lpart[((size_t)rs * HH * CC + row) * CC + t];

    red[t] = v;
    __syncthreads();
#pragma unroll
    for (int s = 128; s > 0; s >>= 1) {
        if (t < s) red[t] = fmaxf(red[t], red[t + s]);
        __syncthreads();
    }
    const float m = red[0];
    __syncthreads();

    const float e = __expf(v - m);
    red[t] = e;
    __syncthreads();
#pragma unroll
    for (int s = 128; s > 0; s >>= 1) {
        if (t < s) red[t] += red[t + s];
        __syncthreads();
    }
    const float p = e / red[0];
    __nv_bfloat16 h, l;
    split_bf16(p, h, l);
    g_ph[row * CC + t] = h;
    g_pl[row * CC + t] = l;
}

// ---------------------------------------------------------------------------
// Stage 4: context. N = 4r x 64d = 256; P tile shared across the 4 r's.
// grid = (2 i-tiles, RR/4, HH). warps 2M x 4N (wx <-> r).
// smem/stage: P(i x 32j) hi+lo 16K; per r: V(32j x 64d) hi 4K + lo 4K.
// ---------------------------------------------------------------------------
__global__ __launch_bounds__(256, 1) void context_mma_kernel()
{
    const int h   = blockIdx.z;
    const int rgb = blockIdx.y * 4;     // 4 r's per CTA
    const int i0  = blockIdx.x * 128;
    const int NJB = CC / BK;            // 8

    extern __shared__ char smem[];
    const uint32_t sb = smem_to_u32(smem);
    const int tid  = threadIdx.x;
    const int lane = tid & 31;
    const int w    = tid >> 5;
    const int wy   = w & 1;             // m warp: i offset wy*64
    const int wx   = w >> 1;            // r index 0..3

    const __nv_bfloat16* Ph = g_ph + (size_t)h * CC * CC;
    const __nv_bfloat16* Pl = g_pl + (size_t)h * CC * CC;

    // A (P) frag addressing: rows ar(mi) = wy*64 + (lane&15) + mi*16, 64B rows
    uint32_t arb[4], axr[4];
#pragma unroll
    for (int mi = 0; mi < 4; mi++) {
        const int ar = wy * 64 + (lane & 15) + mi * 16;
        arb[mi] = (uint32_t)(ar * SROW);
        axr[mi] = (uint32_t)((ar >> 1) & 3);
    }
    const uint32_t acs = (uint32_t)(lane >> 4);

    // B (V) trans frag addressing: per np d-chunk; 128B rows, chunk^(row&7)
    const uint32_t mi_ = (uint32_t)(lane >> 3);
    const uint32_t wi_ = (uint32_t)(lane & 7);
    const uint32_t vjr = (mi_ & 1) * 8 + wi_;    // j row within 16
    const uint32_t vcb = (mi_ >> 1);             // chunk sub-select 0/1
    const uint32_t vreg = CT_B + (uint32_t)wx * 8192;  // this warp's r region

    float acc[4][8][4];
#pragma unroll
    for (int mi = 0; mi < 4; mi++)
#pragma unroll
        for (int nf = 0; nf < 8; nf++)
#pragma unroll
            for (int q = 0; q < 4; q++) acc[mi][nf][q] = 0.0f;

    // loader
    const int pr = tid >> 2, pc = tid & 3;       // P rows, chunks
    const int vr = tid >> 3, vc = tid & 7;       // V rows (j), chunks (d)
    auto cpload_ctx = [&](uint32_t base, int jb) {
        const size_t pgo = (size_t)jb * 32 + pc * 8;
#pragma unroll
        for (int half = 0; half < 2; half++) {
            const int row = pr + half * 64;
            const uint32_t so = swz(row, pc);
            CP16(base + CT_AHI + so, Ph + (size_t)(i0 + row) * CC + pgo);
            CP16(base + CT_ALO + so, Pl + (size_t)(i0 + row) * CC + pgo);
        }
        const uint32_t sv = (uint32_t)(vr * 128) + (uint32_t)(((vc ^ (vr & 7)) << 4));
#pragma unroll
        for (int rr_ = 0; rr_ < 4; rr_++) {
            const size_t vgo = (size_t)((rgb + rr_) * CC + jb * 32 + vr) * EE + h * DD + vc * 8;
            const uint32_t rb = base + CT_B + (uint32_t)rr_ * 8192;
            CP16(rb + sv,        g_vh + vgo);
            CP16(rb + 4096 + sv, g_vl + vgo);
        }
    };

    cpload_ctx(sb, 0);
    CPCOMMIT();
    cpload_ctx(sb + CSTAGE_B, 1);
    CPCOMMIT();

    uint32_t bufo[3] = {sb, sb + CSTAGE_B, sb + 2 * CSTAGE_B};
#pragma unroll 1
    for (int jb = 0; jb < NJB; jb++) {
        if (jb == NJB - 1) { CPWAIT0(); } else { CPWAIT1(); }
        __syncthreads();

        const uint32_t base = bufo[jb % 3];
#pragma unroll
        for (int ks = 0; ks < 2; ks++) {
            const uint32_t ca = acs + (uint32_t)(ks * 2);
            uint32_t ah[4][4], al[4][4];
#pragma unroll
            for (int mi = 0; mi < 4; mi++) {
                LDSM4(ah[mi], base + CT_AHI + arb[mi] + ((ca ^ axr[mi]) << 4));
                LDSM4(al[mi], base + CT_ALO + arb[mi] + ((ca ^ axr[mi]) << 4));
            }
            const uint32_t jrow = vjr + (uint32_t)(ks * 16);
            const uint32_t jbase = base + vreg + jrow * 128;
            const uint32_t jx = (jrow & 7);
#pragma unroll
            for (int np = 0; np < 4; np++) {
                uint32_t bh[4], bl[4];
                const uint32_t c = (uint32_t)(np * 2) + vcb;
                const uint32_t bo = ((c ^ jx) << 4);
                LDSM4T(bh, jbase + bo);
                LDSM4T(bl, jbase + 4096 + bo);
#pragma unroll
                for (int mi = 0; mi < 4; mi++)
                    mma3x2(acc[mi][np * 2], acc[mi][np * 2 + 1],
                           ah[mi], al[mi], bh, bl);
            }
        }

        if (jb + 2 < NJB) {
            cpload_ctx(bufo[(jb + 2) % 3], jb + 2);
            CPCOMMIT();
        }
    }

    // epilogue: warp wx owns r = rgb+wx, d = nf*8 + (lane&3)*2
    const int r = rgb + wx;
    const int mbase = i0 + wy * 64 + (lane >> 2);
    const int dbase = (lane & 3) * 2;
#pragma unroll
    for (int mi = 0; mi < 4; mi++) {
#pragma unroll
        for (int rr = 0; rr < 2; rr++) {
            const int i = mbase + mi * 16 + rr * 8;
            size_t rowo = (size_t)(r * CC + i) * EE + h * DD;
#pragma unroll
            for (int nf = 0; nf < 8; nf++) {
                store_split2(g_ch, g_cl, rowo + dbase + nf * 8,
                             acc[mi][nf][rr * 2], acc[mi][nf][rr * 2 + 1]);
            }
        }
    }
}

// ---------------------------------------------------------------------------
extern "C" void kernel_launch(void* const* d_in, const int* in_sizes, int n_in,
                              void* d_out, int out_size)
{
    (void)in_sizes; (void)n_in; (void)out_size;
    const float* x  = (const float*)d_in[0];
    const float* wq = (const float*)d_in[1];
    const float* bq = (const float*)d_in[2];
    const float* wk = (const float*)d_in[3];
    const float* bk = (const float*)d_in[4];
    const float* wv = (const float*)d_in[5];
    const float* bv = (const float*)d_in[6];
    const float* wo = (const float*)d_in[7];
    const float* bo = (const float*)d_in[8];
    float* out = (float*)d_out;

    static int smem_configured = 0;
    if (!smem_configured) {
        cudaFuncSetAttribute(qkv_mma_kernel,
                             cudaFuncAttributeMaxDynamicSharedMemorySize, GSMEM);
        cudaFuncSetAttribute(out_mma_kernel,
                             cudaFuncAttributeMaxDynamicSharedMemorySize, GSMEM);
        cudaFuncSetAttribute(logits_mma_kernel,
                             cudaFuncAttributeMaxDynamicSharedMemorySize, GSMEM);
        cudaFuncSetAttribute(context_mma_kernel,
                             cudaFuncAttributeMaxDynamicSharedMemorySize, CGSMEM);
        smem_configured = 1;
    }

    pack_x_kernel<<<(MTOK * EE / 4) / 256, 256>>>(x);
    dim3 gw(EE / 32, EE / 32, 4);
    pack_wt_kernel<<<gw, 256>>>(wq, wk, wv, wo);

    dim3 g1(EE / BN, MTOK / BM, 3);               // (3, 256, 3)
    qkv_mma_kernel<<<g1, 256, GSMEM>>>(bq, bk, bv);

    dim3 g2(2, HH, RSPLIT);                       // (2, 12, 16) = 384 CTAs
    logits_mma_kernel<<<g2, 256, GSMEM>>>();

    softmax_kernel<<<HH * CC, 256>>>();

    dim3 g4(2, RR / 4, HH);                       // (2, 32, 12) = 768 CTAs
    context_mma_kernel<<<g4, 256, CGSMEM>>>();

    dim3 g5(EE / BN, MTOK / BM, 1);               // (3, 256)
    out_mma_kernel<<<g5, 256, GSMEM>>>(bo, out);
}